// round 15
// baseline (speedup 1.0000x reference)
#include <cuda_runtime.h>
#include <cuda_bf16.h>

// Cost volume: out[b,h,w,(9i+jj)%81] = (1/H) * sum_c x1[b,h,w,c] * x2[b,h-i,w-jj,c]
// B=8, H=W=C=128, sr=4, D=9, OC=81. Zero padding outside.
//
// Block = (b, band of 2 rows, HALF of the 10 x2 rounds). 1024 blocks (tail-packed).
// 512 threads = 64 w-pairs x 8 c-groups (16ch). A in registers (cp.async slab load).
// B staged via cp.async into double-buffered Bs (row stride 128, XOR swizzle
// c4^((row>>1)&7)); halo rows pre-zeroed. Partials in Ps[g][hr][s][w] (w innermost):
// compute stores STS.64 (conflict-free), flush reads LDS.128 over w (conflict-free).
// Slot s reads Bs[w+s] = x2[r][w+s-4] => jj = 4 - s.

typedef unsigned long long u64;

#define Bb    8
#define Hh    128
#define Ww    128
#define Cc    128
#define OC    81
#define NT    512
#define APAD  68         // A-staging stride: 272B (16B-aligned)

#define BS_FLOATS (136 * 128)          // 17408 per buffer (== A-stage 2*128*68 exactly)
#define PS_FLOATS (8 * 2 * 9 * Ww)     // 18432 ([g][hr][s][w])
#define SMEM_BYTES ((2 * BS_FLOATS + PS_FLOATS) * 4)   // 212992 B

__device__ __forceinline__ u64 fmax2(u64 a, u64 b, u64 c) {
    u64 d;
    asm("fma.rn.f32x2 %0, %1, %2, %3;" : "=l"(d) : "l"(a), "l"(b), "l"(c));
    return d;
}
__device__ __forceinline__ float hsum_x2(u64 p) {
    float lo, hi;
    asm("mov.b64 {%0, %1}, %2;" : "=f"(lo), "=f"(hi) : "l"(p));
    return lo + hi;
}
__device__ __forceinline__ u64 pack2(float lo, float hi) {
    u64 p;
    asm("mov.b64 %0, {%1, %2};" : "=l"(p) : "f"(lo), "f"(hi));
    return p;
}
__device__ __forceinline__ void f4_to_u64(const float4& v, u64& p0, u64& p1) {
    asm("mov.b64 %0, {%1, %2};" : "=l"(p0) : "f"(v.x), "f"(v.y));
    asm("mov.b64 %0, {%1, %2};" : "=l"(p1) : "f"(v.z), "f"(v.w));
}

// Async-stage x2 row r: interior rows only (halo pre-zeroed), branch-free, 4096 LDGSTS.
__device__ __forceinline__ void stage_b_async(const float* __restrict__ x2b,
                                              unsigned bs_u32, int r, int tid) {
    for (int idx = tid; idx < 4096; idx += NT) {
        int wp4 = idx >> 5;                  // 0..127 = w position
        int c4  = idx & 31;
        int wp  = wp4 + 4;                   // Bs row 4..131
        const float* src = x2b + (((r << 7) + wp4) << 7) + (c4 << 2);
        int ce = c4 ^ ((wp >> 1) & 7);
        unsigned dst = bs_u32 + (unsigned)((wp << 7) + (ce << 2)) * 4u;
        asm volatile("cp.async.cg.shared.global [%0], [%1], 16;"
                     :: "r"(dst), "l"(src));
    }
}

// Flush round rr: 576 (or 288) float4 chunks; 8-slab adds; oc once per chunk.
__device__ __forceinline__ void flush_ps(const float* __restrict__ Ps,
                                         float* __restrict__ outb,
                                         int rr, int tid, float invH) {
    const int lo = (rr == 9) ? 1 : 0;
    const int hi = (rr == 0) ? 0 : 1;
    const int nchunks = (hi - lo + 1) * 288;   // per hr: 9 s x 32 w4
    for (int ch = tid; ch < nchunks; ch += NT) {
        int hrl = (ch >= 288) ? 1 : 0;
        int rem = ch - (hrl << 8) - (hrl << 5);   // ch - hrl*288
        int s   = rem >> 5;
        int w4  = rem & 31;
        int hr  = lo + hrl;
        const float* p = Ps + ((hr * 9 + s) << 7) + (w4 << 2);
        float4 v = *reinterpret_cast<const float4*>(p);
#pragma unroll
        for (int g = 1; g < 8; g++) {
            float4 u = *reinterpret_cast<const float4*>(p + g * 2304);
            v.x += u.x; v.y += u.y; v.z += u.z; v.w += u.w;
        }
        int oc = 9 * (hr + 4 - rr) + (4 - s);    // i = h - r, jj = 4 - s
        if (oc < 0) oc += OC;
        size_t ob = (size_t)((hr << 7) + (w4 << 2)) * OC + oc;
        outb[ob]          = v.x * invH;
        outb[ob + OC]     = v.y * invH;
        outb[ob + 2 * OC] = v.z * invH;
        outb[ob + 3 * OC] = v.w * invH;
    }
}

// Invalid x2 row: this half-block still owns round rr's channels -> write zeros.
__device__ __forceinline__ void flush_zero(float* __restrict__ outb,
                                           int rr, int tid) {
    const int lo = (rr == 9) ? 1 : 0;
    const int hi = (rr == 0) ? 0 : 1;
    const int nchunks = (hi - lo + 1) * 288;
    for (int ch = tid; ch < nchunks; ch += NT) {
        int hrl = (ch >= 288) ? 1 : 0;
        int rem = ch - (hrl << 8) - (hrl << 5);
        int s   = rem >> 5;
        int w4  = rem & 31;
        int hr  = lo + hrl;
        int oc = 9 * (hr + 4 - rr) + (4 - s);
        if (oc < 0) oc += OC;
        size_t ob = (size_t)((hr << 7) + (w4 << 2)) * OC + oc;
        outb[ob] = 0.0f; outb[ob + OC] = 0.0f;
        outb[ob + 2 * OC] = 0.0f; outb[ob + 3 * OC] = 0.0f;
    }
}

// One slot pass: slots SOFF..SOFF+2 for both w-positions; 4 B-row loads per k-step.
// Partials stored as STS.64 pairs (wq0, wq1) at Ps[cg][hr][s][w0] — conflict-free.
template<int SOFF>
__device__ __forceinline__ void compute_pass(const u64 a[2][2][8],
                                             const float* __restrict__ Bs,
                                             float* __restrict__ Pmy,
                                             int wp, int w0, int cbase) {
    u64 acc[2][2][3];
#pragma unroll
    for (int hr = 0; hr < 2; hr++)
#pragma unroll
        for (int wq = 0; wq < 2; wq++)
#pragma unroll
            for (int t = 0; t < 3; t++) acc[hr][wq][t] = 0ull;

#pragma unroll
    for (int k = 0; k < 4; k++) {
        u64 b[4][2];
#pragma unroll
        for (int t = 0; t < 4; t++) {
            int R = w0 + SOFF + t;                        // B row
            int x = (wp + ((SOFF + t) >> 1)) & 7;         // (R>>1)&7
            float4 v = *reinterpret_cast<const float4*>(
                Bs + (R << 7) + (((cbase + k) ^ x) << 2));
            f4_to_u64(v, b[t][0], b[t][1]);
        }
#pragma unroll
        for (int hr = 0; hr < 2; hr++)
#pragma unroll
            for (int wq = 0; wq < 2; wq++)
#pragma unroll
                for (int t = 0; t < 3; t++) {
                    acc[hr][wq][t] = fmax2(a[hr][wq][2 * k],     b[wq + t][0], acc[hr][wq][t]);
                    acc[hr][wq][t] = fmax2(a[hr][wq][2 * k + 1], b[wq + t][1], acc[hr][wq][t]);
                }
    }
#pragma unroll
    for (int hr = 0; hr < 2; hr++)
#pragma unroll
        for (int t = 0; t < 3; t++) {
            u64 pr = pack2(hsum_x2(acc[hr][0][t]), hsum_x2(acc[hr][1][t]));
            *reinterpret_cast<u64*>(Pmy + ((hr * 9 + SOFF + t) << 7) + w0) = pr;
        }
}

__global__ void __launch_bounds__(NT, 1)
cost_volume_kernel(const float* __restrict__ x1,
                   const float* __restrict__ x2,
                   float* __restrict__ out) {
    extern __shared__ float sm[];
    float* Bs0 = sm;                       // [136][128] swizzled, parity 0
    float* Bs1 = sm + BS_FLOATS;           // parity 1; also A-staging slab at init
    float* Ps  = sm + 2 * BS_FLOATS;       // [8][2][9][128] partials per c-group

    const int tid  = threadIdx.x;
    const int wp   = tid & 63;                // w-pair index
    const int w0   = wp << 1;
    const int cg   = tid >> 6;                // c-group 0..7 (16 ch at cg*16)
    const int cbase = cg << 2;                // float4 col base
    const int bx   = blockIdx.x;
    const int half = bx & 1;                  // rounds 0-4 or 5-9
    const int h0   = ((bx >> 1) & 63) << 1;
    const int bblk = bx >> 7;
    const int rr0  = half * 5;
    const float invH = 1.0f / 128.0f;

    const float* x1b  = x1 + ((size_t)(bblk * Hh + h0)) * (Ww * Cc);
    const float* x2b  = x2 + ((size_t)bblk) * (Hh * Ww * Cc);
    float*       outb = out + ((size_t)(bblk * Hh + h0)) * (Ww * OC);

    const unsigned bs0_u32  = (unsigned)__cvta_generic_to_shared(Bs0);
    const unsigned bs1_u32  = (unsigned)__cvta_generic_to_shared(Bs1);
    const unsigned slab_u32 = bs1_u32;

    // Prologue: async-stage first round's B row into Bs0 (interior only).
    {
        int r0 = h0 - 4 + rr0;
        if ((unsigned)r0 < (unsigned)Hh) stage_b_async(x2b, bs0_u32, r0, tid);
        asm volatile("cp.async.commit_group;");
    }

    // ---- Load A into registers via cp.async slab (2 c-halves through Bs1) ----
    u64 a[2][2][8];
#pragma unroll
    for (int hc = 0; hc < 2; hc++) {
        for (int idx = tid; idx < 2 * Ww * 16; idx += NT) {
            int row = idx >> 11;
            int rem = idx & 2047;
            int ww  = rem >> 4;
            int c4  = rem & 15;
            const float* src = x1b + (((row << 7) + ww) << 7) + (hc << 6) + (c4 << 2);
            unsigned dst = slab_u32 + (unsigned)((row * Ww + ww) * APAD + (c4 << 2)) * 4u;
            asm volatile("cp.async.cg.shared.global [%0], [%1], 16;"
                         :: "r"(dst), "l"(src));
        }
        asm volatile("cp.async.commit_group;");
        asm volatile("cp.async.wait_group 0;");
        __syncthreads();
        if ((cg >> 2) == hc) {
            const int cl = (cg & 3) << 4;
#pragma unroll
            for (int hr = 0; hr < 2; hr++)
#pragma unroll
                for (int wq = 0; wq < 2; wq++)
#pragma unroll
                    for (int k = 0; k < 4; k++) {
                        float4 v = *reinterpret_cast<const float4*>(
                            Bs1 + (hr * Ww + w0 + wq) * APAD + cl + (k << 2));
                        f4_to_u64(v, a[hr][wq][2 * k], a[hr][wq][2 * k + 1]);
                    }
        }
        __syncthreads();
    }

    // Zero halo rows (0-3, 132-135) of BOTH buffers once.
    {
        int b   = tid >> 8;
        int rem = tid & 255;
        int hrw = rem >> 5;
        int row = hrw + ((hrw >= 4) ? 128 : 0);
        int c4  = rem & 31;
        float* bp = b ? Bs1 : Bs0;
        *reinterpret_cast<float4*>(bp + (row << 7) + (c4 << 2)) =
            make_float4(0.f, 0.f, 0.f, 0.f);
    }

    // ---- Main loop over this half's 5 rounds ----
    float* Pmy = Ps + cg * 2304;
    for (int j = 0; j < 5; j++) {
        const int rrg = rr0 + j;
        const int r = h0 - 4 + rrg;
        const bool rvalid = ((unsigned)r < (unsigned)Hh);

        // 1. Issue next round's staging into the other buffer.
        if (j < 4) {
            int rn = r + 1;
            if ((unsigned)rn < (unsigned)Hh)
                stage_b_async(x2b, (j & 1) ? bs0_u32 : bs1_u32, rn, tid);
        }
        asm volatile("cp.async.commit_group;");   // uniform group count

        // Invalid round: our channels still need zeros (overlaps cp.async copies).
        if (!rvalid) flush_zero(outb, rrg, tid);

        // 2. Wait for THIS round's staging.
        asm volatile("cp.async.wait_group 1;");
        __syncthreads();

        // 3. Compute round rrg.
        if (rvalid) {
            const float* Bcur = (j & 1) ? Bs1 : Bs0;
            compute_pass<0>(a, Bcur, Pmy, wp, w0, cbase);
            compute_pass<3>(a, Bcur, Pmy, wp, w0, cbase);
            compute_pass<6>(a, Bcur, Pmy, wp, w0, cbase);
        }
        __syncthreads();

        // 4. Flush round rrg (cp.async of round rrg+1 still in flight underneath).
        if (rvalid) flush_ps(Ps, outb, rrg, tid, invH);
    }
}

extern "C" void kernel_launch(void* const* d_in, const int* in_sizes, int n_in,
                              void* d_out, int out_size) {
    const float* x1 = (const float*)d_in[0];
    const float* x2 = (const float*)d_in[1];
    float* out = (float*)d_out;

    static bool attr_set = false;
    if (!attr_set) {
        cudaFuncSetAttribute(cost_volume_kernel,
                             cudaFuncAttributeMaxDynamicSharedMemorySize, SMEM_BYTES);
        attr_set = true;
    }

    dim3 grid(Bb * 64 * 2);  // 1024 half-blocks
    cost_volume_kernel<<<grid, NT, SMEM_BYTES>>>(x1, x2, out);
}

// round 16
// speedup vs baseline: 1.1760x; 1.1760x over previous
#include <cuda_runtime.h>
#include <cuda_bf16.h>

// Cost volume: out[b,h,w,(9i+jj)%81] = (1/H) * sum_c x1[b,h,w,c] * x2[b,h-i,w-jj,c]
// B=8, H=W=C=128, sr=4, D=9, OC=81. Zero padding outside.
//
// Block = (b, band of 2 rows, HALF of the 10 x2 rounds). 1024 blocks (tail-packed).
// Halves own disjoint output channels -> independent, write-once.
// 512 threads = 64 w-pairs x 8 c-groups (16ch). A in registers (cp.async slab load).
// B staged via cp.async into double-buffered Bs (row stride 128, XOR swizzle
// c4^((row>>1)&7)); halo rows pre-zeroed. Partials in Ps[g][hr][w][s] (s innermost:
// keeps output STGs in ~36-element contiguous runs — R15 showed w-innermost scatters
// STG and blows L2). Output stores use __stwt (write-once, keep L2 for x2 reuse).
// Slot s reads Bs[w+s] = x2[r][w+s-4] => jj = 4 - s.

typedef unsigned long long u64;

#define Bb    8
#define Hh    128
#define Ww    128
#define Cc    128
#define OC    81
#define NT    512
#define APAD  68         // A-staging stride: 272B (16B-aligned)

#define BS_FLOATS (136 * 128)          // 17408 per buffer (== A-stage 2*128*68 exactly)
#define PS_FLOATS (8 * 2 * Ww * 9)     // 18432 ([g][hr][w][s])
#define SMEM_BYTES ((2 * BS_FLOATS + PS_FLOATS) * 4)   // 212992 B

__device__ __forceinline__ u64 fmax2(u64 a, u64 b, u64 c) {
    u64 d;
    asm("fma.rn.f32x2 %0, %1, %2, %3;" : "=l"(d) : "l"(a), "l"(b), "l"(c));
    return d;
}
__device__ __forceinline__ float hsum_x2(u64 p) {
    float lo, hi;
    asm("mov.b64 {%0, %1}, %2;" : "=f"(lo), "=f"(hi) : "l"(p));
    return lo + hi;
}
__device__ __forceinline__ void f4_to_u64(const float4& v, u64& p0, u64& p1) {
    asm("mov.b64 %0, {%1, %2};" : "=l"(p0) : "f"(v.x), "f"(v.y));
    asm("mov.b64 %0, {%1, %2};" : "=l"(p1) : "f"(v.z), "f"(v.w));
}

// Async-stage x2 row r: interior rows only (halo pre-zeroed), branch-free, 4096 LDGSTS.
__device__ __forceinline__ void stage_b_async(const float* __restrict__ x2b,
                                              unsigned bs_u32, int r, int tid) {
    for (int idx = tid; idx < 4096; idx += NT) {
        int wp4 = idx >> 5;                  // 0..127 = w position
        int c4  = idx & 31;
        int wp  = wp4 + 4;                   // Bs row 4..131
        const float* src = x2b + (((r << 7) + wp4) << 7) + (c4 << 2);
        int ce = c4 ^ ((wp >> 1) & 7);
        unsigned dst = bs_u32 + (unsigned)((wp << 7) + (ce << 2)) * 4u;
        asm volatile("cp.async.cg.shared.global [%0], [%1], 16;"
                     :: "r"(dst), "l"(src));
    }
}

// Sum 8 c-group partials, scale, write final outputs for global round rr.
// Incremental (pos, s) indexing: NT = 56*9 + 8. s-fastest keeps STGs contiguous.
__device__ __forceinline__ void flush_ps(const float* __restrict__ Ps,
                                         float* __restrict__ outb,
                                         int rr, int tid, float invH) {
    const int lo = (rr == 9) ? 1 : 0;
    const int hi = (rr == 0) ? 0 : 1;
    const int total = (hi - lo + 1) * Ww * 9;
    int pos = tid / 9;                 // output index within (rows x 128 w)
    int s   = tid - pos * 9;
    const int obase = lo * Ww;         // first active (rw*Ww) offset
    for (int idx = tid; idx < total; idx += NT) {
        int off = (obase + pos) * 9 + s;
        float v = 0.0f;
#pragma unroll
        for (int g = 0; g < 8; g++) v += Ps[g * 2304 + off];
        int rw = lo + (pos >> 7);
        int oc = 9 * (rw + 4 - rr) + (4 - s);   // i = h - r, jj = 4 - s
        if (oc < 0) oc += OC;
        int ww = pos & 127;
        __stwt(&outb[(size_t)(rw * Ww + ww) * OC + oc], v * invH);
        pos += 56; s += 8;
        if (s >= 9) { s -= 9; pos++; }
    }
}

// Invalid x2 row: this half-block still owns round rr's channels -> write zeros.
__device__ __forceinline__ void flush_zero(float* __restrict__ outb,
                                           int rr, int tid) {
    const int lo = (rr == 9) ? 1 : 0;
    const int hi = (rr == 0) ? 0 : 1;
    const int total = (hi - lo + 1) * Ww * 9;
    int pos = tid / 9;
    int s   = tid - pos * 9;
    for (int idx = tid; idx < total; idx += NT) {
        int rw = lo + (pos >> 7);
        int oc = 9 * (rw + 4 - rr) + (4 - s);
        if (oc < 0) oc += OC;
        int ww = pos & 127;
        __stwt(&outb[(size_t)(rw * Ww + ww) * OC + oc], 0.0f);
        pos += 56; s += 8;
        if (s >= 9) { s -= 9; pos++; }
    }
}

// One slot pass: slots SOFF..SOFF+2 for both w-positions; 4 B-row loads per k-step.
template<int SOFF>
__device__ __forceinline__ void compute_pass(const u64 a[2][2][8],
                                             const float* __restrict__ Bs,
                                             float* __restrict__ Pmy,
                                             int wp, int w0, int cbase) {
    u64 acc[2][2][3];
#pragma unroll
    for (int hr = 0; hr < 2; hr++)
#pragma unroll
        for (int wq = 0; wq < 2; wq++)
#pragma unroll
            for (int t = 0; t < 3; t++) acc[hr][wq][t] = 0ull;

#pragma unroll
    for (int k = 0; k < 4; k++) {
        u64 b[4][2];
#pragma unroll
        for (int t = 0; t < 4; t++) {
            int R = w0 + SOFF + t;                        // B row
            int x = (wp + ((SOFF + t) >> 1)) & 7;         // (R>>1)&7
            float4 v = *reinterpret_cast<const float4*>(
                Bs + (R << 7) + (((cbase + k) ^ x) << 2));
            f4_to_u64(v, b[t][0], b[t][1]);
        }
#pragma unroll
        for (int hr = 0; hr < 2; hr++)
#pragma unroll
            for (int wq = 0; wq < 2; wq++)
#pragma unroll
                for (int t = 0; t < 3; t++) {
                    acc[hr][wq][t] = fmax2(a[hr][wq][2 * k],     b[wq + t][0], acc[hr][wq][t]);
                    acc[hr][wq][t] = fmax2(a[hr][wq][2 * k + 1], b[wq + t][1], acc[hr][wq][t]);
                }
    }
#pragma unroll
    for (int hr = 0; hr < 2; hr++)
#pragma unroll
        for (int wq = 0; wq < 2; wq++)
#pragma unroll
            for (int t = 0; t < 3; t++)
                Pmy[(hr * Ww + w0 + wq) * 9 + SOFF + t] = hsum_x2(acc[hr][wq][t]);
}

__global__ void __launch_bounds__(NT, 1)
cost_volume_kernel(const float* __restrict__ x1,
                   const float* __restrict__ x2,
                   float* __restrict__ out) {
    extern __shared__ float sm[];
    float* Bs0 = sm;                       // [136][128] swizzled, parity 0
    float* Bs1 = sm + BS_FLOATS;           // parity 1; also A-staging slab at init
    float* Ps  = sm + 2 * BS_FLOATS;       // [8][2][128][9] partials per c-group

    const int tid  = threadIdx.x;
    const int wp   = tid & 63;                // w-pair index
    const int w0   = wp << 1;
    const int cg   = tid >> 6;                // c-group 0..7 (16 ch at cg*16)
    const int cbase = cg << 2;                // float4 col base
    const int bx   = blockIdx.x;
    const int half = bx & 1;                  // rounds 0-4 or 5-9
    const int h0   = ((bx >> 1) & 63) << 1;
    const int bblk = bx >> 7;
    const int rr0  = half * 5;
    const float invH = 1.0f / 128.0f;

    const float* x1b  = x1 + ((size_t)(bblk * Hh + h0)) * (Ww * Cc);
    const float* x2b  = x2 + ((size_t)bblk) * (Hh * Ww * Cc);
    float*       outb = out + ((size_t)(bblk * Hh + h0)) * (Ww * OC);

    const unsigned bs0_u32  = (unsigned)__cvta_generic_to_shared(Bs0);
    const unsigned bs1_u32  = (unsigned)__cvta_generic_to_shared(Bs1);
    const unsigned slab_u32 = bs1_u32;

    // Prologue: async-stage first round's B row into Bs0 (interior only).
    {
        int r0 = h0 - 4 + rr0;
        if ((unsigned)r0 < (unsigned)Hh) stage_b_async(x2b, bs0_u32, r0, tid);
        asm volatile("cp.async.commit_group;");
    }

    // ---- Load A into registers via cp.async slab (2 c-halves through Bs1) ----
    u64 a[2][2][8];
#pragma unroll
    for (int hc = 0; hc < 2; hc++) {
        for (int idx = tid; idx < 2 * Ww * 16; idx += NT) {
            int row = idx >> 11;
            int rem = idx & 2047;
            int ww  = rem >> 4;
            int c4  = rem & 15;
            const float* src = x1b + (((row << 7) + ww) << 7) + (hc << 6) + (c4 << 2);
            unsigned dst = slab_u32 + (unsigned)((row * Ww + ww) * APAD + (c4 << 2)) * 4u;
            asm volatile("cp.async.cg.shared.global [%0], [%1], 16;"
                         :: "r"(dst), "l"(src));
        }
        asm volatile("cp.async.commit_group;");
        asm volatile("cp.async.wait_group 0;");   // also drains prologue B group (harmless)
        __syncthreads();
        if ((cg >> 2) == hc) {
            const int cl = (cg & 3) << 4;
#pragma unroll
            for (int hr = 0; hr < 2; hr++)
#pragma unroll
                for (int wq = 0; wq < 2; wq++)
#pragma unroll
                    for (int k = 0; k < 4; k++) {
                        float4 v = *reinterpret_cast<const float4*>(
                            Bs1 + (hr * Ww + w0 + wq) * APAD + cl + (k << 2));
                        f4_to_u64(v, a[hr][wq][2 * k], a[hr][wq][2 * k + 1]);
                    }
        }
        __syncthreads();
    }

    // Zero halo rows (0-3, 132-135) of BOTH buffers once. 512 float4 stores.
    {
        int b   = tid >> 8;            // buffer 0/1
        int rem = tid & 255;
        int hrw = rem >> 5;            // 0..7
        int row = hrw + ((hrw >= 4) ? 128 : 0);
        int c4  = rem & 31;
        float* bp = b ? Bs1 : Bs0;
        *reinterpret_cast<float4*>(bp + (row << 7) + (c4 << 2)) =
            make_float4(0.f, 0.f, 0.f, 0.f);
    }

    // ---- Main loop over this half's 5 rounds ----
    float* Pmy = Ps + cg * 2304;
    for (int j = 0; j < 5; j++) {
        const int rrg = rr0 + j;
        const int r = h0 - 4 + rrg;
        const bool rvalid = ((unsigned)r < (unsigned)Hh);

        // 1. Issue next round's staging into the other buffer.
        if (j < 4) {
            int rn = r + 1;
            if ((unsigned)rn < (unsigned)Hh)
                stage_b_async(x2b, (j & 1) ? bs0_u32 : bs1_u32, rn, tid);
        }
        asm volatile("cp.async.commit_group;");   // uniform group count

        // Invalid round: our channels still need zeros (overlaps cp.async copies).
        if (!rvalid) flush_zero(outb, rrg, tid);

        // 2. Wait for THIS round's staging.
        asm volatile("cp.async.wait_group 1;");
        __syncthreads();

        // 3. Compute round rrg.
        if (rvalid) {
            const float* Bcur = (j & 1) ? Bs1 : Bs0;
            compute_pass<0>(a, Bcur, Pmy, wp, w0, cbase);
            compute_pass<3>(a, Bcur, Pmy, wp, w0, cbase);
            compute_pass<6>(a, Bcur, Pmy, wp, w0, cbase);
        }
        __syncthreads();

        // 4. Flush round rrg (cp.async of round rrg+1 still in flight underneath).
        if (rvalid) flush_ps(Ps, outb, rrg, tid, invH);
    }
}

extern "C" void kernel_launch(void* const* d_in, const int* in_sizes, int n_in,
                              void* d_out, int out_size) {
    const float* x1 = (const float*)d_in[0];
    const float* x2 = (const float*)d_in[1];
    float* out = (float*)d_out;

    static bool attr_set = false;
    if (!attr_set) {
        cudaFuncSetAttribute(cost_volume_kernel,
                             cudaFuncAttributeMaxDynamicSharedMemorySize, SMEM_BYTES);
        attr_set = true;
    }

    dim3 grid(Bb * 64 * 2);  // 1024 half-blocks
    cost_volume_kernel<<<grid, NT, SMEM_BYTES>>>(x1, x2, out);
}